// round 14
// baseline (speedup 1.0000x reference)
#include <cuda_runtime.h>
#include <cstdint>

#define TS   2048
#define TDK  64
#define TBH  32
#define CTX_ELEMS (TBH*TS*TDK)          /* 4,194,304  */
#define ATT_WORDS 4194304u

// ---------------- device scratch ---------------------------------------------
__device__ float2   g_part[TBH * TS * 16];   // per (row, ktile): (max, sumexp)
__device__ float    g_scale[TBH * TS * 16];  // per (row, ktile): exp(mx_t-m)/S
__device__ unsigned g_keep[ATT_WORDS];       // dropout keep bits

// ---------------- packed f32x2 helpers ---------------------------------------
__device__ __forceinline__ unsigned long long fma2(unsigned long long a,
                                                   unsigned long long b,
                                                   unsigned long long c) {
    unsigned long long d;
    asm("fma.rn.f32x2 %0, %1, %2, %3;" : "=l"(d) : "l"(a), "l"(b), "l"(c));
    return d;
}
__device__ __forceinline__ unsigned long long dup2(float s) {
    unsigned long long d;
    asm("mov.b64 %0, {%1, %1};" : "=l"(d) : "f"(s));
    return d;
}
__device__ __forceinline__ float2 unpk(unsigned long long v) {
    float2 r;
    asm("mov.b64 {%0, %1}, %2;" : "=f"(r.x), "=f"(r.y) : "l"(v));
    return r;
}
// integer add routed to the fma pipe (IMAD) — `one` must be opaque to ptxas
__device__ __forceinline__ unsigned madd(unsigned a, unsigned one, unsigned c) {
    unsigned d;
    asm("mad.lo.u32 %0, %1, %2, %3;" : "=r"(d) : "r"(a), "r"(one), "r"(c));
    return d;
}

// ---------------- JAX threefry2x32 (key = (0, 42)), partitionable ------------
// Adds issued as IMAD (fma pipe) via `one`; rot/xor stay on the alu pipe.
__device__ __forceinline__ unsigned tf_bits(unsigned c1, unsigned one) {
    const unsigned k1 = 42u, k2 = 0x1BD11BDAu ^ 42u;
    unsigned x0 = 0u, x1 = c1 + k1;
#define TFR(r) do { x0 = madd(x1, one, x0); \
                    x1 = __funnelshift_l(x1, x1, (r)); x1 ^= x0; } while (0)
    TFR(13); TFR(15); TFR(26); TFR(6);
    x0 = madd(k1, one, x0);      x1 = madd(k2 + 1u, one, x1);
    TFR(17); TFR(29); TFR(16); TFR(24);
    x0 = madd(k2, one, x0);      x1 = madd(2u, one, x1);
    TFR(13); TFR(15); TFR(26); TFR(6);
    /* x0 += k0 (=0) */          x1 = madd(k1 + 3u, one, x1);
    TFR(17); TFR(29); TFR(16); TFR(24);
    x0 = madd(k1, one, x0);      x1 = madd(k2 + 4u, one, x1);
    TFR(13); TFR(15); TFR(26); TFR(6);
    x0 = madd(k2, one, x0);      x1 = madd(5u, one, x1);
#undef TFR
    return x0 ^ x1;
}

// ---------------- K1: scores GEMM + RNG interleaved, pair-duplicated Q -------
// 64q x 128k tile, 256 threads, 3 blocks/SM. Warp: tx=tid&31 owns k=tx*4
// (2 f32x2 pairs, warp covers full 128k once), ty=tid>>5, q=ty+8j.
// Q stored in smem as (q,q) PAIRS so a-operands load directly as f32x2
// broadcasts (no per-fma dup2 MOVs). 2 threefry draws per c-chunk on the
// alu+fma pipes. Stores exp(s - mx_tile); K3 rescales with g_scale.
__global__ __launch_bounds__(256, 3) void scores_kernel(
    const float* __restrict__ Q, const float* __restrict__ Km,
    const float* __restrict__ mask, float* __restrict__ scores) {
    extern __shared__ float sm[];
    float* Qs = sm;             // [64][132]  duplicated pairs
    float* Kt = sm + 64 * 132;  // [64][132]  d-major

    const int bh    = blockIdx.z;
    const int b     = bh >> 4;
    const int qBase = blockIdx.y * 64;
    const int kBase = blockIdx.x * 128;
    const int tid   = threadIdx.x;
    const unsigned one = blockDim.x >> 8;   // == 1, opaque to ptxas

    const float* Qg = Q  + ((size_t)bh * TS + qBase) * TDK;
    const float* Kg = Km + ((size_t)bh * TS + kBase) * TDK;

#pragma unroll
    for (int i = 0; i < 4; i++) {
        int f = tid + i * 256, r = f >> 4, c4 = f & 15;
        float4 v = *(const float4*)(Qg + r * 64 + c4 * 4);
        *(float4*)(Qs + r * 132 + c4 * 8)     = make_float4(v.x, v.x, v.y, v.y);
        *(float4*)(Qs + r * 132 + c4 * 8 + 4) = make_float4(v.z, v.z, v.w, v.w);
    }
#pragma unroll
    for (int i = 0; i < 8; i++) {
        int f = tid + i * 256, r = f >> 4, c4 = f & 15;   // r = k row 0..127
        float4 kv = *(const float4*)(Kg + r * 64 + c4 * 4);
#pragma unroll
        for (int u = 0; u < 4; u++) {
            int d = c4 * 4 + u;
            int s = ((d >> 3) & 3) << 3;
            float vv = (u == 0) ? kv.x : (u == 1) ? kv.y : (u == 2) ? kv.z : kv.w;
            Kt[d * 132 + (r ^ s)] = vv;
        }
    }
    __syncthreads();

    const int tx = tid & 31, ty = tid >> 5;

    const unsigned i0 = ((unsigned)(bh * TS + qBase + (tid >> 2))) * (unsigned)TS
                        + (unsigned)kBase + (unsigned)(tid & 3) * 32u;
    unsigned w0 = 0u;

    unsigned long long acc[8][2];
#pragma unroll
    for (int j = 0; j < 8; j++) { acc[j][0] = 0ull; acc[j][1] = 0ull; }

#pragma unroll
    for (int c = 0; c < 16; c++) {
        // two threefry draws, alu+fma balanced
        {
            int e = c * 2;
            w0 |= ((~tf_bits(i0 + (unsigned)e, one)) >> 31) << e;
            w0 |= ((~tf_bits(i0 + (unsigned)e + 1u, one)) >> 31) << (e + 1);
        }
        ulonglong2 bb[4];
#pragma unroll
        for (int dd = 0; dd < 4; dd++) {
            int d = c * 4 + dd;
            int s = ((d >> 3) & 3) << 3;
            bb[dd] = *(const ulonglong2*)(Kt + d * 132 + ((tx << 2) ^ s));
        }
#pragma unroll
        for (int j = 0; j < 8; j++) {
            const float* qp = Qs + (ty + 8 * j) * 132 + c * 8;
            ulonglong2 p01 = *(const ulonglong2*)(qp);       // (a0,a0),(a1,a1)
            ulonglong2 p23 = *(const ulonglong2*)(qp + 4);   // (a2,a2),(a3,a3)
            acc[j][0] = fma2(p01.x, bb[0].x, acc[j][0]);
            acc[j][1] = fma2(p01.x, bb[0].y, acc[j][1]);
            acc[j][0] = fma2(p01.y, bb[1].x, acc[j][0]);
            acc[j][1] = fma2(p01.y, bb[1].y, acc[j][1]);
            acc[j][0] = fma2(p23.x, bb[2].x, acc[j][0]);
            acc[j][1] = fma2(p23.x, bb[2].y, acc[j][1]);
            acc[j][0] = fma2(p23.y, bb[3].x, acc[j][0]);
            acc[j][1] = fma2(p23.y, bb[3].y, acc[j][1]);
        }
    }
    g_keep[i0 >> 5] = w0;

    // epilogue: mask, tile max, store exp(s - mx_tile), tile stats
    const float* mrow = mask + (size_t)b * TS * TS;
#pragma unroll
    for (int j = 0; j < 8; j++) {
        int q = qBase + ty + 8 * j;
        float4 m0 = *(const float4*)(mrow + (size_t)q * TS + kBase + tx * 4);
        float2 p0 = unpk(acc[j][0]), p1 = unpk(acc[j][1]);
        float s0 = fmaf(p0.x, 0.125f, (m0.x - 1.0f) * 1e9f);
        float s1 = fmaf(p0.y, 0.125f, (m0.y - 1.0f) * 1e9f);
        float s2 = fmaf(p1.x, 0.125f, (m0.z - 1.0f) * 1e9f);
        float s3 = fmaf(p1.y, 0.125f, (m0.w - 1.0f) * 1e9f);

        float mx = fmaxf(fmaxf(s0, s1), fmaxf(s2, s3));
#pragma unroll
        for (int o = 16; o > 0; o >>= 1)
            mx = fmaxf(mx, __shfl_xor_sync(0xffffffffu, mx, o));
        float t0 = __expf(s0 - mx), t1 = __expf(s1 - mx);
        float t2 = __expf(s2 - mx), t3 = __expf(s3 - mx);
        *(float4*)(scores + ((size_t)bh * TS + q) * TS + kBase + tx * 4) =
            make_float4(t0, t1, t2, t3);
        float e = t0 + t1 + t2 + t3;
#pragma unroll
        for (int o = 16; o > 0; o >>= 1)
            e += __shfl_xor_sync(0xffffffffu, e, o);
        if (tx == 0)
            g_part[((size_t)bh * TS + q) * 16 + blockIdx.x] = make_float2(mx, e);
    }
}

// ---------------- K2: tile partials -> per-(row,ktile) rescale ---------------
__global__ __launch_bounds__(256) void reduce_kernel() {
    unsigned row = blockIdx.x * 256u + threadIdx.x;
    const float2* pp = &g_part[(size_t)row * 16];
    float2 p[16];
#pragma unroll
    for (int t = 0; t < 16; t++) p[t] = pp[t];
    float m = p[0].x;
#pragma unroll
    for (int t = 1; t < 16; t++) m = fmaxf(m, p[t].x);
    float s = 0.f;
#pragma unroll
    for (int t = 0; t < 16; t++) s += p[t].y * __expf(p[t].x - m);
    float inv = 1.0f / s;
#pragma unroll
    for (int t = 0; t < 16; t++)
        g_scale[(size_t)row * 16 + t] = __expf(p[t].x - m) * inv;
}

// ---------------- K3: pipelined attn rescale + dropout + (P_drop @ V) --------
// (unchanged from round 13: 64q x 64dv, 256 thr, 4 blocks/SM, attn+keep
//  register pipeline, V direct to smem at transform time)
__global__ __launch_bounds__(256, 4) void context_kernel(
    const float* __restrict__ V, float* __restrict__ attn, float* __restrict__ ctx) {
    extern __shared__ float sm[];
    float* Ps  = sm;                       // [64][68]
    float* Vs  = sm + 64 * 68;             // [64][68]
    float* scs = sm + 128 * 68;            // [64][16]

    const int bh    = blockIdx.z;
    const int qBase = blockIdx.x * 64;
    const int tid   = threadIdx.x;
    const int tx    = tid & 15, ty = tid >> 4;

#pragma unroll
    for (int i = 0; i < 4; i++) {
        int x = tid + i * 256;
        scs[x] = g_scale[((size_t)bh * TS + qBase + (x >> 4)) * 16 + (x & 15)];
    }
    __syncthreads();

    unsigned long long acc2[4][2];
#pragma unroll
    for (int j = 0; j < 4; j++) { acc2[j][0] = 0ull; acc2[j][1] = 0ull; }

    const float* Vg = V + (size_t)bh * TS * TDK;

    float4   atv[4];
    unsigned kw[4];
#pragma unroll
    for (int i = 0; i < 4; i++) {
        int f = tid + i * 256, r = f >> 4, c4 = f & 15;
        size_t off = ((size_t)bh * TS + qBase + r) * TS + c4 * 4;
        atv[i] = *(const float4*)(attn + off);
        kw[i]  = g_keep[off >> 5];
    }

    for (int c = 0; c < 32; c++) {
        const int kBase = c * 64;
#pragma unroll
        for (int i = 0; i < 4; i++) {
            int f = tid + i * 256, r = f >> 4, c4 = f & 15;
            float4 vq = *(const float4*)(Vg + (size_t)(kBase + r) * TDK + c4 * 4);
            *(float4*)(Vs + r * 68 + c4 * 4) = vq;

            int q = qBase + r, k = kBase + c4 * 4;
            size_t off = ((size_t)bh * TS + q) * TS + k;
            float sc = scs[r * 16 + (c >> 1)];
            float4 p;
            p.x = atv[i].x * sc; p.y = atv[i].y * sc;
            p.z = atv[i].z * sc; p.w = atv[i].w * sc;
            *(float4*)(attn + off) = p;               // normalized attn out
            int bit = (int)(off & 31u);
            float4 pd;
            pd.x = ((kw[i] >> bit)       & 1u) ? p.x + p.x : 0.f;
            pd.y = ((kw[i] >> (bit + 1)) & 1u) ? p.y + p.y : 0.f;
            pd.z = ((kw[i] >> (bit + 2)) & 1u) ? p.z + p.z : 0.f;
            pd.w = ((kw[i] >> (bit + 3)) & 1u) ? p.w + p.w : 0.f;
            *(float4*)(Ps + r * 68 + c4 * 4) = pd;
        }
        __syncthreads();

        if (c < 31) {
            const int kn = (c + 1) * 64;
#pragma unroll
            for (int i = 0; i < 4; i++) {
                int f = tid + i * 256, r = f >> 4, c4 = f & 15;
                size_t off = ((size_t)bh * TS + qBase + r) * TS + kn + c4 * 4;
                atv[i] = *(const float4*)(attn + off);
                kw[i]  = g_keep[off >> 5];
            }
        }

#pragma unroll
        for (int kk4 = 0; kk4 < 16; kk4++) {
            float4 av[4];
#pragma unroll
            for (int j = 0; j < 4; j++)
                av[j] = *(const float4*)(Ps + (ty + 16 * j) * 68 + kk4 * 4);
#pragma unroll
            for (int t = 0; t < 4; t++) {
                ulonglong2 bv = *(const ulonglong2*)(Vs + (kk4 * 4 + t) * 68 + tx * 4);
#pragma unroll
                for (int j = 0; j < 4; j++) {
                    float as = (t == 0) ? av[j].x : (t == 1) ? av[j].y :
                               (t == 2) ? av[j].z : av[j].w;
                    unsigned long long a2 = dup2(as);
                    acc2[j][0] = fma2(a2, bv.x, acc2[j][0]);
                    acc2[j][1] = fma2(a2, bv.y, acc2[j][1]);
                }
            }
        }
        __syncthreads();
    }

#pragma unroll
    for (int j = 0; j < 4; j++) {
        int q = qBase + ty + 16 * j;
        float2 lo = unpk(acc2[j][0]), hi = unpk(acc2[j][1]);
        *(float4*)(ctx + ((size_t)bh * TS + q) * TDK + tx * 4) =
            make_float4(lo.x, lo.y, hi.x, hi.y);
    }
}

// ---------------- launch -----------------------------------------------------
extern "C" void kernel_launch(void* const* d_in, const int* in_sizes, int n_in,
                              void* d_out, int out_size) {
    const float* Q    = (const float*)d_in[0];
    const float* K    = (const float*)d_in[1];
    const float* V    = (const float*)d_in[2];
    const float* mask = (const float*)d_in[3];

    float* ctx  = (float*)d_out;            // context first (reference return order)
    float* attn = ctx + CTX_ELEMS;          // then attn; also used as scores scratch

    cudaFuncSetAttribute(scores_kernel,  cudaFuncAttributeMaxDynamicSharedMemorySize, 67584);
    cudaFuncSetAttribute(context_kernel, cudaFuncAttributeMaxDynamicSharedMemorySize, 38912);

    scores_kernel<<<dim3(16, 32, 32), 256, 67584>>>(Q, K, mask, attn);
    reduce_kernel<<<256, 256>>>();
    context_kernel<<<dim3(32, 1, 32), 256, 38912>>>(V, attn, ctx);
}

// round 15
// speedup vs baseline: 1.1621x; 1.1621x over previous
#include <cuda_runtime.h>
#include <cstdint>

#define TS   2048
#define TDK  64
#define TBH  32
#define CTX_ELEMS (TBH*TS*TDK)          /* 4,194,304  */

// ---------------- device scratch ---------------------------------------------
__device__ float2 g_part[TBH * TS * 16];   // per (row, ktile): (max, sumexp_tile)
__device__ float  g_scale[TBH * TS * 16];  // per (row, ktile): exp(mx_t-m)/S

// ---------------- packed f32x2 helpers ---------------------------------------
__device__ __forceinline__ unsigned long long fma2(unsigned long long a,
                                                   unsigned long long b,
                                                   unsigned long long c) {
    unsigned long long d;
    asm("fma.rn.f32x2 %0, %1, %2, %3;" : "=l"(d) : "l"(a), "l"(b), "l"(c));
    return d;
}
__device__ __forceinline__ unsigned long long dup2(float s) {
    unsigned long long d;
    asm("mov.b64 %0, {%1, %1};" : "=l"(d) : "f"(s));
    return d;
}
__device__ __forceinline__ float2 unpk(unsigned long long v) {
    float2 r;
    asm("mov.b64 {%0, %1}, %2;" : "=f"(r.x), "=f"(r.y) : "l"(v));
    return r;
}

// ---------------- JAX threefry2x32 (key = (0, 42)), partitionable ------------
__device__ __forceinline__ void tf_round(unsigned& x0, unsigned& x1, int r) {
    x0 += x1;
    x1 = __funnelshift_l(x1, x1, r);
    x1 ^= x0;
}
__device__ __forceinline__ unsigned tf_bits(unsigned c1) {
    const unsigned k0 = 0u, k1 = 42u, k2 = 0x1BD11BDAu ^ 42u;
    unsigned x0 = 0u + k0, x1 = c1 + k1;
    tf_round(x0,x1,13); tf_round(x0,x1,15); tf_round(x0,x1,26); tf_round(x0,x1, 6);
    x0 += k1; x1 += k2 + 1u;
    tf_round(x0,x1,17); tf_round(x0,x1,29); tf_round(x0,x1,16); tf_round(x0,x1,24);
    x0 += k2; x1 += k0 + 2u;
    tf_round(x0,x1,13); tf_round(x0,x1,15); tf_round(x0,x1,26); tf_round(x0,x1, 6);
    x0 += k0; x1 += k1 + 3u;
    tf_round(x0,x1,17); tf_round(x0,x1,29); tf_round(x0,x1,16); tf_round(x0,x1,24);
    x0 += k1; x1 += k2 + 4u;
    tf_round(x0,x1,13); tf_round(x0,x1,15); tf_round(x0,x1,26); tf_round(x0,x1, 6);
    x0 += k2; x1 += k0 + 5u;
    return x0 ^ x1;
}
// 2.0 if kept (inverse keep-prob), 0.0 if dropped: uniform<0.5 <=> MSB clear
__device__ __forceinline__ float keep2x(unsigned e) {
    return ((~tf_bits(e)) >> 31) ? 2.0f : 0.0f;
}

// ---------------- K1: tile-exp'd scores + per-(row,ktile) stats --------------
// EXACT round-9 structure (measured 433us): 64q x 128k, 256 thr, 3 blocks/SM.
// Warp: tx=tid&31 owns k=tx*4 (2 f32x2 pairs), ty=tid>>5, q=ty+8j.
// Stores exp(s - mx_tile); K3 rescales with g_scale. No RNG here.
__global__ __launch_bounds__(256, 3) void scores_kernel(
    const float* __restrict__ Q, const float* __restrict__ Km,
    const float* __restrict__ mask, float* __restrict__ scores) {
    extern __shared__ float sm[];
    float* Qs = sm;            // [64][68]
    float* Kt = sm + 64 * 68;  // [64][132]  d-major

    const int bh    = blockIdx.z;
    const int b     = bh >> 4;
    const int qBase = blockIdx.y * 64;
    const int kBase = blockIdx.x * 128;
    const int tid   = threadIdx.x;

    const float* Qg = Q  + ((size_t)bh * TS + qBase) * TDK;
    const float* Kg = Km + ((size_t)bh * TS + kBase) * TDK;

#pragma unroll
    for (int i = 0; i < 4; i++) {
        int f = tid + i * 256, r = f >> 4, c4 = f & 15;
        *(float4*)(Qs + r * 68 + c4 * 4) = *(const float4*)(Qg + r * 64 + c4 * 4);
    }
#pragma unroll
    for (int i = 0; i < 8; i++) {
        int f = tid + i * 256, r = f >> 4, c4 = f & 15;   // r = k row 0..127
        float4 kv = *(const float4*)(Kg + r * 64 + c4 * 4);
#pragma unroll
        for (int u = 0; u < 4; u++) {
            int d = c4 * 4 + u;
            int s = ((d >> 3) & 3) << 3;
            float vv = (u == 0) ? kv.x : (u == 1) ? kv.y : (u == 2) ? kv.z : kv.w;
            Kt[d * 132 + (r ^ s)] = vv;
        }
    }
    __syncthreads();

    const int tx = tid & 31, ty = tid >> 5;

    unsigned long long acc[8][2];
#pragma unroll
    for (int j = 0; j < 8; j++) { acc[j][0] = 0ull; acc[j][1] = 0ull; }

#pragma unroll
    for (int c = 0; c < 16; c++) {
        ulonglong2 bb[4];
#pragma unroll
        for (int dd = 0; dd < 4; dd++) {
            int d = c * 4 + dd;
            int s = ((d >> 3) & 3) << 3;
            bb[dd] = *(const ulonglong2*)(Kt + d * 132 + ((tx << 2) ^ s));
        }
#pragma unroll
        for (int j = 0; j < 8; j++) {
            float4 a = *(const float4*)(Qs + (ty + 8 * j) * 68 + c * 4);
            unsigned long long a0 = dup2(a.x), a1 = dup2(a.y);
            unsigned long long a2 = dup2(a.z), a3 = dup2(a.w);
            acc[j][0] = fma2(a0, bb[0].x, acc[j][0]);
            acc[j][1] = fma2(a0, bb[0].y, acc[j][1]);
            acc[j][0] = fma2(a1, bb[1].x, acc[j][0]);
            acc[j][1] = fma2(a1, bb[1].y, acc[j][1]);
            acc[j][0] = fma2(a2, bb[2].x, acc[j][0]);
            acc[j][1] = fma2(a2, bb[2].y, acc[j][1]);
            acc[j][0] = fma2(a3, bb[3].x, acc[j][0]);
            acc[j][1] = fma2(a3, bb[3].y, acc[j][1]);
        }
    }

    // epilogue: mask, tile max, store exp(s - mx_tile), tile stats
    const float* mrow = mask + (size_t)b * TS * TS;
#pragma unroll
    for (int j = 0; j < 8; j++) {
        int q = qBase + ty + 8 * j;
        float4 m0 = *(const float4*)(mrow + (size_t)q * TS + kBase + tx * 4);
        float2 p0 = unpk(acc[j][0]), p1 = unpk(acc[j][1]);
        float s0 = fmaf(p0.x, 0.125f, (m0.x - 1.0f) * 1e9f);
        float s1 = fmaf(p0.y, 0.125f, (m0.y - 1.0f) * 1e9f);
        float s2 = fmaf(p1.x, 0.125f, (m0.z - 1.0f) * 1e9f);
        float s3 = fmaf(p1.y, 0.125f, (m0.w - 1.0f) * 1e9f);

        float mx = fmaxf(fmaxf(s0, s1), fmaxf(s2, s3));
#pragma unroll
        for (int o = 16; o > 0; o >>= 1)
            mx = fmaxf(mx, __shfl_xor_sync(0xffffffffu, mx, o));
        float t0 = __expf(s0 - mx), t1 = __expf(s1 - mx);
        float t2 = __expf(s2 - mx), t3 = __expf(s3 - mx);
        *(float4*)(scores + ((size_t)bh * TS + q) * TS + kBase + tx * 4) =
            make_float4(t0, t1, t2, t3);
        float e = t0 + t1 + t2 + t3;
#pragma unroll
        for (int o = 16; o > 0; o >>= 1)
            e += __shfl_xor_sync(0xffffffffu, e, o);
        if (tx == 0)
            g_part[((size_t)bh * TS + q) * 16 + blockIdx.x] = make_float2(mx, e);
    }
}

// ---------------- K2: tile partials -> per-(row,ktile) rescale ---------------
__global__ __launch_bounds__(256) void reduce_kernel() {
    unsigned row = blockIdx.x * 256u + threadIdx.x;
    const float2* pp = &g_part[(size_t)row * 16];
    float2 p[16];
#pragma unroll
    for (int t = 0; t < 16; t++) p[t] = pp[t];
    float m = p[0].x;
#pragma unroll
    for (int t = 1; t < 16; t++) m = fmaxf(m, p[t].x);
    float s = 0.f;
#pragma unroll
    for (int t = 0; t < 16; t++) s += p[t].y * __expf(p[t].x - m);
    float inv = 1.0f / s;
#pragma unroll
    for (int t = 0; t < 16; t++)
        g_scale[(size_t)row * 16 + t] = __expf(p[t].x - m) * inv;
}

// ---------------- K3: pipelined rescale + INLINE threefry dropout + PV -------
// 64q x 64dv tile, 256 threads, 4 blocks/SM (32 warps/SM). attn loads
// register-pipelined one chunk ahead; V direct to smem (L2-hot); dropout keep
// bits computed inline (threefry on alu pipe fills issue bubbles).
__global__ __launch_bounds__(256, 4) void context_kernel(
    const float* __restrict__ V, float* __restrict__ attn, float* __restrict__ ctx) {
    extern __shared__ float sm[];
    float* Ps  = sm;                       // [64][68]
    float* Vs  = sm + 64 * 68;             // [64][68]
    float* scs = sm + 128 * 68;            // [64][16]

    const int bh    = blockIdx.z;
    const int qBase = blockIdx.x * 64;
    const int tid   = threadIdx.x;
    const int tx    = tid & 15, ty = tid >> 4;

#pragma unroll
    for (int i = 0; i < 4; i++) {
        int x = tid + i * 256;
        scs[x] = g_scale[((size_t)bh * TS + qBase + (x >> 4)) * 16 + (x & 15)];
    }
    __syncthreads();

    unsigned long long acc2[4][2];
#pragma unroll
    for (int j = 0; j < 4; j++) { acc2[j][0] = 0ull; acc2[j][1] = 0ull; }

    const float* Vg = V + (size_t)bh * TS * TDK;

    // ---- prefetch chunk 0 (attn only) ----
    float4 atv[4];
#pragma unroll
    for (int i = 0; i < 4; i++) {
        int f = tid + i * 256, r = f >> 4, c4 = f & 15;
        size_t off = ((size_t)bh * TS + qBase + r) * TS + c4 * 4;
        atv[i] = *(const float4*)(attn + off);
    }

    for (int c = 0; c < 32; c++) {
        const int kBase = c * 64;
        // ---- transform phase: V loads, rescale, inline-RNG dropout ----
#pragma unroll
        for (int i = 0; i < 4; i++) {
            int f = tid + i * 256, r = f >> 4, c4 = f & 15;
            float4 vq = *(const float4*)(Vg + (size_t)(kBase + r) * TDK + c4 * 4);
            *(float4*)(Vs + r * 68 + c4 * 4) = vq;

            int q = qBase + r, k = kBase + c4 * 4;
            size_t off = ((size_t)bh * TS + q) * TS + k;
            unsigned e0 = (unsigned)off;
            float sc = scs[r * 16 + (c >> 1)];
            float4 p;
            p.x = atv[i].x * sc; p.y = atv[i].y * sc;
            p.z = atv[i].z * sc; p.w = atv[i].w * sc;
            *(float4*)(attn + off) = p;               // normalized attn out
            float4 pd;
            pd.x = p.x * keep2x(e0);
            pd.y = p.y * keep2x(e0 + 1u);
            pd.z = p.z * keep2x(e0 + 2u);
            pd.w = p.w * keep2x(e0 + 3u);
            *(float4*)(Ps + r * 68 + c4 * 4) = pd;
        }
        __syncthreads();

        // ---- prefetch chunk c+1 attn (in flight during GEMM) ----
        if (c < 31) {
            const int kn = (c + 1) * 64;
#pragma unroll
            for (int i = 0; i < 4; i++) {
                int f = tid + i * 256, r = f >> 4, c4 = f & 15;
                size_t off = ((size_t)bh * TS + qBase + r) * TS + kn + c4 * 4;
                atv[i] = *(const float4*)(attn + off);
            }
        }

        // ---- GEMM phase ----
#pragma unroll
        for (int kk4 = 0; kk4 < 16; kk4++) {
            float4 av[4];
#pragma unroll
            for (int j = 0; j < 4; j++)
                av[j] = *(const float4*)(Ps + (ty + 16 * j) * 68 + kk4 * 4);
#pragma unroll
            for (int t = 0; t < 4; t++) {
                ulonglong2 bv = *(const ulonglong2*)(Vs + (kk4 * 4 + t) * 68 + tx * 4);
#pragma unroll
                for (int j = 0; j < 4; j++) {
                    float as = (t == 0) ? av[j].x : (t == 1) ? av[j].y :
                               (t == 2) ? av[j].z : av[j].w;
                    unsigned long long a2 = dup2(as);
                    acc2[j][0] = fma2(a2, bv.x, acc2[j][0]);
                    acc2[j][1] = fma2(a2, bv.y, acc2[j][1]);
                }
            }
        }
        __syncthreads();
    }

#pragma unroll
    for (int j = 0; j < 4; j++) {
        int q = qBase + ty + 16 * j;
        float2 lo = unpk(acc2[j][0]), hi = unpk(acc2[j][1]);
        *(float4*)(ctx + ((size_t)bh * TS + q) * TDK + tx * 4) =
            make_float4(lo.x, lo.y, hi.x, hi.y);
    }
}

// ---------------- launch -----------------------------------------------------
extern "C" void kernel_launch(void* const* d_in, const int* in_sizes, int n_in,
                              void* d_out, int out_size) {
    const float* Q    = (const float*)d_in[0];
    const float* K    = (const float*)d_in[1];
    const float* V    = (const float*)d_in[2];
    const float* mask = (const float*)d_in[3];

    float* ctx  = (float*)d_out;            // context first (reference return order)
    float* attn = ctx + CTX_ELEMS;          // then attn; also used as scores scratch

    cudaFuncSetAttribute(scores_kernel,  cudaFuncAttributeMaxDynamicSharedMemorySize, 51200);
    cudaFuncSetAttribute(context_kernel, cudaFuncAttributeMaxDynamicSharedMemorySize, 38912);

    scores_kernel<<<dim3(16, 32, 32), 256, 51200>>>(Q, K, mask, attn);
    reduce_kernel<<<256, 256>>>();
    context_kernel<<<dim3(32, 1, 32), 256, 38912>>>(V, attn, ctx);
}

// round 16
// speedup vs baseline: 1.1781x; 1.0138x over previous
#include <cuda_runtime.h>
#include <cstdint>

#define TS   2048
#define TDK  64
#define TBH  32
#define CTX_ELEMS (TBH*TS*TDK)          /* 4,194,304  */

// ---------------- device scratch ---------------------------------------------
__device__ float2 g_part[TBH * TS * 16];   // per (row, ktile): (max, sumexp_tile)
__device__ float  g_scale[TBH * TS * 16];  // per (row, ktile): exp(mx_t-m)/S

// ---------------- packed f32x2 helpers ---------------------------------------
__device__ __forceinline__ unsigned long long fma2(unsigned long long a,
                                                   unsigned long long b,
                                                   unsigned long long c) {
    unsigned long long d;
    asm("fma.rn.f32x2 %0, %1, %2, %3;" : "=l"(d) : "l"(a), "l"(b), "l"(c));
    return d;
}
__device__ __forceinline__ unsigned long long dup2(float s) {
    unsigned long long d;
    asm("mov.b64 %0, {%1, %1};" : "=l"(d) : "f"(s));
    return d;
}
__device__ __forceinline__ float2 unpk(unsigned long long v) {
    float2 r;
    asm("mov.b64 {%0, %1}, %2;" : "=f"(r.x), "=f"(r.y) : "l"(v));
    return r;
}

// ---------------- JAX threefry2x32 (key = (0, 42)), partitionable ------------
__device__ __forceinline__ void tf_round(unsigned& x0, unsigned& x1, int r) {
    x0 += x1;
    x1 = __funnelshift_l(x1, x1, r);
    x1 ^= x0;
}
__device__ __forceinline__ unsigned tf_bits(unsigned c1) {
    const unsigned k0 = 0u, k1 = 42u, k2 = 0x1BD11BDAu ^ 42u;
    unsigned x0 = 0u + k0, x1 = c1 + k1;
    tf_round(x0,x1,13); tf_round(x0,x1,15); tf_round(x0,x1,26); tf_round(x0,x1, 6);
    x0 += k1; x1 += k2 + 1u;
    tf_round(x0,x1,17); tf_round(x0,x1,29); tf_round(x0,x1,16); tf_round(x0,x1,24);
    x0 += k2; x1 += k0 + 2u;
    tf_round(x0,x1,13); tf_round(x0,x1,15); tf_round(x0,x1,26); tf_round(x0,x1, 6);
    x0 += k0; x1 += k1 + 3u;
    tf_round(x0,x1,17); tf_round(x0,x1,29); tf_round(x0,x1,16); tf_round(x0,x1,24);
    x0 += k1; x1 += k2 + 4u;
    tf_round(x0,x1,13); tf_round(x0,x1,15); tf_round(x0,x1,26); tf_round(x0,x1, 6);
    x0 += k2; x1 += k0 + 5u;
    return x0 ^ x1;
}
// 2.0 if kept (inverse keep-prob), 0.0 if dropped: uniform<0.5 <=> MSB clear
__device__ __forceinline__ float keep2x(unsigned e) {
    return ((~tf_bits(e)) >> 31) ? 2.0f : 0.0f;
}

// ---------------- K1: tile-exp'd scores + per-(row,ktile) stats --------------
// 128q x 128k tile, 256 threads, 2 blocks/SM. Per-thread 8q x 8k microtile:
// tx=tid&15 owns k=tx*8 (4 f32x2 pairs), ty=tid>>4, q=ty+16j (j<8).
// b-loads are 16-address half-warp broadcasts; a-loads 2-address broadcasts.
// 33% less crossbar traffic per fma2 than the 8q x 4k layout.
// Stores exp(s - mx_tile); K3 rescales with g_scale. No RNG here.
__global__ __launch_bounds__(256, 2) void scores_kernel(
    const float* __restrict__ Q, const float* __restrict__ Km,
    const float* __restrict__ mask, float* __restrict__ scores) {
    extern __shared__ float sm[];
    float* Qs = sm;             // [128][68]
    float* Kt = sm + 128 * 68;  // [64][132]  d-major

    const int bh    = blockIdx.z;
    const int b     = bh >> 4;
    const int qBase = blockIdx.y * 128;
    const int kBase = blockIdx.x * 128;
    const int tid   = threadIdx.x;

    const float* Qg = Q  + ((size_t)bh * TS + qBase) * TDK;
    const float* Kg = Km + ((size_t)bh * TS + kBase) * TDK;

#pragma unroll
    for (int i = 0; i < 8; i++) {
        int f = tid + i * 256, r = f >> 4, c4 = f & 15;
        *(float4*)(Qs + r * 68 + c4 * 4) = *(const float4*)(Qg + r * 64 + c4 * 4);
    }
#pragma unroll
    for (int i = 0; i < 8; i++) {
        int f = tid + i * 256, r = f >> 4, c4 = f & 15;   // r = k row 0..127
        float4 kv = *(const float4*)(Kg + r * 64 + c4 * 4);
#pragma unroll
        for (int u = 0; u < 4; u++) {
            int d = c4 * 4 + u;
            int s = ((d >> 3) & 3) << 3;
            float vv = (u == 0) ? kv.x : (u == 1) ? kv.y : (u == 2) ? kv.z : kv.w;
            Kt[d * 132 + (r ^ s)] = vv;
        }
    }
    __syncthreads();

    const int tx = tid & 15, ty = tid >> 4;

    unsigned long long acc[8][4];
#pragma unroll
    for (int j = 0; j < 8; j++)
#pragma unroll
        for (int p = 0; p < 4; p++) acc[j][p] = 0ull;

#pragma unroll
    for (int c = 0; c < 16; c++) {
        ulonglong2 bb[4][2];
#pragma unroll
        for (int dd = 0; dd < 4; dd++) {
            int d = c * 4 + dd;
            int s = ((d >> 3) & 3) << 3;
            const float* kr = Kt + d * 132 + ((tx << 3) ^ s);
            bb[dd][0] = *(const ulonglong2*)(kr);
            bb[dd][1] = *(const ulonglong2*)(kr + 4);
        }
#pragma unroll
        for (int j = 0; j < 8; j++) {
            float4 a = *(const float4*)(Qs + (ty + 16 * j) * 68 + c * 4);
            unsigned long long a0 = dup2(a.x), a1 = dup2(a.y);
            unsigned long long a2 = dup2(a.z), a3 = dup2(a.w);
            acc[j][0] = fma2(a0, bb[0][0].x, acc[j][0]);
            acc[j][1] = fma2(a0, bb[0][0].y, acc[j][1]);
            acc[j][2] = fma2(a0, bb[0][1].x, acc[j][2]);
            acc[j][3] = fma2(a0, bb[0][1].y, acc[j][3]);
            acc[j][0] = fma2(a1, bb[1][0].x, acc[j][0]);
            acc[j][1] = fma2(a1, bb[1][0].y, acc[j][1]);
            acc[j][2] = fma2(a1, bb[1][1].x, acc[j][2]);
            acc[j][3] = fma2(a1, bb[1][1].y, acc[j][3]);
            acc[j][0] = fma2(a2, bb[2][0].x, acc[j][0]);
            acc[j][1] = fma2(a2, bb[2][0].y, acc[j][1]);
            acc[j][2] = fma2(a2, bb[2][1].x, acc[j][2]);
            acc[j][3] = fma2(a2, bb[2][1].y, acc[j][3]);
            acc[j][0] = fma2(a3, bb[3][0].x, acc[j][0]);
            acc[j][1] = fma2(a3, bb[3][0].y, acc[j][1]);
            acc[j][2] = fma2(a3, bb[3][1].x, acc[j][2]);
            acc[j][3] = fma2(a3, bb[3][1].y, acc[j][3]);
        }
    }

    // epilogue: mask, tile max (16-lane reduce), store exp(s - mx), stats
    const float* mrow = mask + (size_t)b * TS * TS;
#pragma unroll
    for (int j = 0; j < 8; j++) {
        int q = qBase + ty + 16 * j;
        const float* mp = mrow + (size_t)q * TS + kBase + tx * 8;
        float4 m0 = *(const float4*)(mp);
        float4 m1 = *(const float4*)(mp + 4);
        float2 p0 = unpk(acc[j][0]), p1 = unpk(acc[j][1]);
        float2 p2 = unpk(acc[j][2]), p3 = unpk(acc[j][3]);
        float s0 = fmaf(p0.x, 0.125f, (m0.x - 1.0f) * 1e9f);
        float s1 = fmaf(p0.y, 0.125f, (m0.y - 1.0f) * 1e9f);
        float s2 = fmaf(p1.x, 0.125f, (m0.z - 1.0f) * 1e9f);
        float s3 = fmaf(p1.y, 0.125f, (m0.w - 1.0f) * 1e9f);
        float s4 = fmaf(p2.x, 0.125f, (m1.x - 1.0f) * 1e9f);
        float s5 = fmaf(p2.y, 0.125f, (m1.y - 1.0f) * 1e9f);
        float s6 = fmaf(p3.x, 0.125f, (m1.z - 1.0f) * 1e9f);
        float s7 = fmaf(p3.y, 0.125f, (m1.w - 1.0f) * 1e9f);

        float mx = fmaxf(fmaxf(fmaxf(s0, s1), fmaxf(s2, s3)),
                         fmaxf(fmaxf(s4, s5), fmaxf(s6, s7)));
#pragma unroll
        for (int o = 8; o > 0; o >>= 1)
            mx = fmaxf(mx, __shfl_xor_sync(0xffffffffu, mx, o));
        float t0 = __expf(s0 - mx), t1 = __expf(s1 - mx);
        float t2 = __expf(s2 - mx), t3 = __expf(s3 - mx);
        float t4 = __expf(s4 - mx), t5 = __expf(s5 - mx);
        float t6 = __expf(s6 - mx), t7 = __expf(s7 - mx);
        float* op = scores + ((size_t)bh * TS + q) * TS + kBase + tx * 8;
        *(float4*)(op)     = make_float4(t0, t1, t2, t3);
        *(float4*)(op + 4) = make_float4(t4, t5, t6, t7);
        float e = t0 + t1 + t2 + t3 + t4 + t5 + t6 + t7;
#pragma unroll
        for (int o = 8; o > 0; o >>= 1)
            e += __shfl_xor_sync(0xffffffffu, e, o);
        if (tx == 0)
            g_part[((size_t)bh * TS + q) * 16 + blockIdx.x] = make_float2(mx, e);
    }
}

// ---------------- K2: tile partials -> per-(row,ktile) rescale ---------------
__global__ __launch_bounds__(256) void reduce_kernel() {
    unsigned row = blockIdx.x * 256u + threadIdx.x;
    const float2* pp = &g_part[(size_t)row * 16];
    float2 p[16];
#pragma unroll
    for (int t = 0; t < 16; t++) p[t] = pp[t];
    float m = p[0].x;
#pragma unroll
    for (int t = 1; t < 16; t++) m = fmaxf(m, p[t].x);
    float s = 0.f;
#pragma unroll
    for (int t = 0; t < 16; t++) s += p[t].y * __expf(p[t].x - m);
    float inv = 1.0f / s;
#pragma unroll
    for (int t = 0; t < 16; t++)
        g_scale[(size_t)row * 16 + t] = __expf(p[t].x - m) * inv;
}

// ---------------- K3: pipelined rescale + INLINE threefry dropout + PV -------
// (unchanged from round 15: 64q x 64dv, 256 thr, 4 blocks/SM)
__global__ __launch_bounds__(256, 4) void context_kernel(
    const float* __restrict__ V, float* __restrict__ attn, float* __restrict__ ctx) {
    extern __shared__ float sm[];
    float* Ps  = sm;                       // [64][68]
    float* Vs  = sm + 64 * 68;             // [64][68]
    float* scs = sm + 128 * 68;            // [64][16]

    const int bh    = blockIdx.z;
    const int qBase = blockIdx.x * 64;
    const int tid   = threadIdx.x;
    const int tx    = tid & 15, ty = tid >> 4;

#pragma unroll
    for (int i = 0; i < 4; i++) {
        int x = tid + i * 256;
        scs[x] = g_scale[((size_t)bh * TS + qBase + (x >> 4)) * 16 + (x & 15)];
    }
    __syncthreads();

    unsigned long long acc2[4][2];
#pragma unroll
    for (int j = 0; j < 4; j++) { acc2[j][0] = 0ull; acc2[j][1] = 0ull; }

    const float* Vg = V + (size_t)bh * TS * TDK;

    float4 atv[4];
#pragma unroll
    for (int i = 0; i < 4; i++) {
        int f = tid + i * 256, r = f >> 4, c4 = f & 15;
        size_t off = ((size_t)bh * TS + qBase + r) * TS + c4 * 4;
        atv[i] = *(const float4*)(attn + off);
    }

    for (int c = 0; c < 32; c++) {
        const int kBase = c * 64;
#pragma unroll
        for (int i = 0; i < 4; i++) {
            int f = tid + i * 256, r = f >> 4, c4 = f & 15;
            float4 vq = *(const float4*)(Vg + (size_t)(kBase + r) * TDK + c4 * 4);
            *(float4*)(Vs + r * 68 + c4 * 4) = vq;

            int q = qBase + r, k = kBase + c4 * 4;
            size_t off = ((size_t)bh * TS + q) * TS + k;
            unsigned e0 = (unsigned)off;
            float sc = scs[r * 16 + (c >> 1)];
            float4 p;
            p.x = atv[i].x * sc; p.y = atv[i].y * sc;
            p.z = atv[i].z * sc; p.w = atv[i].w * sc;
            *(float4*)(attn + off) = p;               // normalized attn out
            float4 pd;
            pd.x = p.x * keep2x(e0);
            pd.y = p.y * keep2x(e0 + 1u);
            pd.z = p.z * keep2x(e0 + 2u);
            pd.w = p.w * keep2x(e0 + 3u);
            *(float4*)(Ps + r * 68 + c4 * 4) = pd;
        }
        __syncthreads();

        if (c < 31) {
            const int kn = (c + 1) * 64;
#pragma unroll
            for (int i = 0; i < 4; i++) {
                int f = tid + i * 256, r = f >> 4, c4 = f & 15;
                size_t off = ((size_t)bh * TS + qBase + r) * TS + kn + c4 * 4;
                atv[i] = *(const float4*)(attn + off);
            }
        }

#pragma unroll
        for (int kk4 = 0; kk4 < 16; kk4++) {
            float4 av[4];
#pragma unroll
            for (int j = 0; j < 4; j++)
                av[j] = *(const float4*)(Ps + (ty + 16 * j) * 68 + kk4 * 4);
#pragma unroll
            for (int t = 0; t < 4; t++) {
                ulonglong2 bv = *(const ulonglong2*)(Vs + (kk4 * 4 + t) * 68 + tx * 4);
#pragma unroll
                for (int j = 0; j < 4; j++) {
                    float as = (t == 0) ? av[j].x : (t == 1) ? av[j].y :
                               (t == 2) ? av[j].z : av[j].w;
                    unsigned long long a2 = dup2(as);
                    acc2[j][0] = fma2(a2, bv.x, acc2[j][0]);
                    acc2[j][1] = fma2(a2, bv.y, acc2[j][1]);
                }
            }
        }
        __syncthreads();
    }

#pragma unroll
    for (int j = 0; j < 4; j++) {
        int q = qBase + ty + 16 * j;
        float2 lo = unpk(acc2[j][0]), hi = unpk(acc2[j][1]);
        *(float4*)(ctx + ((size_t)bh * TS + q) * TDK + tx * 4) =
            make_float4(lo.x, lo.y, hi.x, hi.y);
    }
}

// ---------------- launch -----------------------------------------------------
extern "C" void kernel_launch(void* const* d_in, const int* in_sizes, int n_in,
                              void* d_out, int out_size) {
    const float* Q    = (const float*)d_in[0];
    const float* K    = (const float*)d_in[1];
    const float* V    = (const float*)d_in[2];
    const float* mask = (const float*)d_in[3];

    float* ctx  = (float*)d_out;            // context first (reference return order)
    float* attn = ctx + CTX_ELEMS;          // then attn; also used as scores scratch

    cudaFuncSetAttribute(scores_kernel,  cudaFuncAttributeMaxDynamicSharedMemorySize, 68608);
    cudaFuncSetAttribute(context_kernel, cudaFuncAttributeMaxDynamicSharedMemorySize, 38912);

    scores_kernel<<<dim3(16, 16, 32), 256, 68608>>>(Q, K, mask, attn);
    reduce_kernel<<<256, 256>>>();
    context_kernel<<<dim3(32, 1, 32), 256, 38912>>>(V, attn, ctx);
}

// round 17
// speedup vs baseline: 1.2015x; 1.0198x over previous
#include <cuda_runtime.h>
#include <cstdint>

#define TS   2048
#define TDK  64
#define TBH  32
#define CTX_ELEMS (TBH*TS*TDK)          /* 4,194,304  */

// ---------------- device scratch ---------------------------------------------
__device__ float2 g_part[TBH * TS * 16];   // per (row, ktile): (max, sumexp_tile)
__device__ float  g_scale[TBH * TS * 16];  // per (row, ktile): exp(mx_t-m)/S

// ---------------- packed f32x2 helpers ---------------------------------------
__device__ __forceinline__ unsigned long long fma2(unsigned long long a,
                                                   unsigned long long b,
                                                   unsigned long long c) {
    unsigned long long d;
    asm("fma.rn.f32x2 %0, %1, %2, %3;" : "=l"(d) : "l"(a), "l"(b), "l"(c));
    return d;
}
__device__ __forceinline__ unsigned long long dup2(float s) {
    unsigned long long d;
    asm("mov.b64 %0, {%1, %1};" : "=l"(d) : "f"(s));
    return d;
}
__device__ __forceinline__ float2 unpk(unsigned long long v) {
    float2 r;
    asm("mov.b64 {%0, %1}, %2;" : "=f"(r.x), "=f"(r.y) : "l"(v));
    return r;
}

// ---------------- JAX threefry2x32 (key = (0, 42)), partitionable ------------
__device__ __forceinline__ void tf_round(unsigned& x0, unsigned& x1, int r) {
    x0 += x1;
    x1 = __funnelshift_l(x1, x1, r);
    x1 ^= x0;
}
__device__ __forceinline__ unsigned tf_bits(unsigned c1) {
    const unsigned k0 = 0u, k1 = 42u, k2 = 0x1BD11BDAu ^ 42u;
    unsigned x0 = 0u + k0, x1 = c1 + k1;
    tf_round(x0,x1,13); tf_round(x0,x1,15); tf_round(x0,x1,26); tf_round(x0,x1, 6);
    x0 += k1; x1 += k2 + 1u;
    tf_round(x0,x1,17); tf_round(x0,x1,29); tf_round(x0,x1,16); tf_round(x0,x1,24);
    x0 += k2; x1 += k0 + 2u;
    tf_round(x0,x1,13); tf_round(x0,x1,15); tf_round(x0,x1,26); tf_round(x0,x1, 6);
    x0 += k0; x1 += k1 + 3u;
    tf_round(x0,x1,17); tf_round(x0,x1,29); tf_round(x0,x1,16); tf_round(x0,x1,24);
    x0 += k1; x1 += k2 + 4u;
    tf_round(x0,x1,13); tf_round(x0,x1,15); tf_round(x0,x1,26); tf_round(x0,x1, 6);
    x0 += k2; x1 += k0 + 5u;
    return x0 ^ x1;
}
// 2.0 if kept (inverse keep-prob), 0.0 if dropped: uniform<0.5 <=> MSB clear
__device__ __forceinline__ float keep2x(unsigned e) {
    return ((~tf_bits(e)) >> 31) ? 2.0f : 0.0f;
}

// ---------------- K1: tile-exp'd scores + per-(row,ktile) stats --------------
// 128q x 128k tile, 256 threads, 2 blocks/SM. Per-thread 8q x 8k microtile
// with CONFLICT-FREE split-k ownership: thread (tx,ty) owns
// k in {tx*4..tx*4+3} and {64+tx*4..64+tx*4+3} — each b-load is a 16-lane
// 16B-stride contiguous LDS.128 (zero bank conflicts; +64 commutes with the
// bit-3/4 xor swizzle). a-loads are 2-address broadcasts.
// Stores exp(s - mx_tile); K3 rescales with g_scale. No RNG here.
__global__ __launch_bounds__(256, 2) void scores_kernel(
    const float* __restrict__ Q, const float* __restrict__ Km,
    const float* __restrict__ mask, float* __restrict__ scores) {
    extern __shared__ float sm[];
    float* Qs = sm;             // [128][68]
    float* Kt = sm + 128 * 68;  // [64][132]  d-major

    const int bh    = blockIdx.z;
    const int b     = bh >> 4;
    const int qBase = blockIdx.y * 128;
    const int kBase = blockIdx.x * 128;
    const int tid   = threadIdx.x;

    const float* Qg = Q  + ((size_t)bh * TS + qBase) * TDK;
    const float* Kg = Km + ((size_t)bh * TS + kBase) * TDK;

#pragma unroll
    for (int i = 0; i < 8; i++) {
        int f = tid + i * 256, r = f >> 4, c4 = f & 15;
        *(float4*)(Qs + r * 68 + c4 * 4) = *(const float4*)(Qg + r * 64 + c4 * 4);
    }
#pragma unroll
    for (int i = 0; i < 8; i++) {
        int f = tid + i * 256, r = f >> 4, c4 = f & 15;   // r = k row 0..127
        float4 kv = *(const float4*)(Kg + r * 64 + c4 * 4);
#pragma unroll
        for (int u = 0; u < 4; u++) {
            int d = c4 * 4 + u;
            int s = ((d >> 3) & 3) << 3;
            float vv = (u == 0) ? kv.x : (u == 1) ? kv.y : (u == 2) ? kv.z : kv.w;
            Kt[d * 132 + (r ^ s)] = vv;
        }
    }
    __syncthreads();

    const int tx = tid & 15, ty = tid >> 4;

    unsigned long long acc[8][4];   // [j][0..1]=k lo group, [2..3]=k hi group
#pragma unroll
    for (int j = 0; j < 8; j++)
#pragma unroll
        for (int p = 0; p < 4; p++) acc[j][p] = 0ull;

#pragma unroll
    for (int c = 0; c < 16; c++) {
        ulonglong2 bb[4][2];
#pragma unroll
        for (int dd = 0; dd < 4; dd++) {
            int d = c * 4 + dd;
            int s = ((d >> 3) & 3) << 3;
            const float* kr = Kt + d * 132 + ((tx << 2) ^ s);
            bb[dd][0] = *(const ulonglong2*)(kr);        // k = tx*4   .. +3
            bb[dd][1] = *(const ulonglong2*)(kr + 64);   // k = 64+tx*4.. +3
        }
#pragma unroll
        for (int j = 0; j < 8; j++) {
            float4 a = *(const float4*)(Qs + (ty + 16 * j) * 68 + c * 4);
            unsigned long long a0 = dup2(a.x), a1 = dup2(a.y);
            unsigned long long a2 = dup2(a.z), a3 = dup2(a.w);
            acc[j][0] = fma2(a0, bb[0][0].x, acc[j][0]);
            acc[j][1] = fma2(a0, bb[0][0].y, acc[j][1]);
            acc[j][2] = fma2(a0, bb[0][1].x, acc[j][2]);
            acc[j][3] = fma2(a0, bb[0][1].y, acc[j][3]);
            acc[j][0] = fma2(a1, bb[1][0].x, acc[j][0]);
            acc[j][1] = fma2(a1, bb[1][0].y, acc[j][1]);
            acc[j][2] = fma2(a1, bb[1][1].x, acc[j][2]);
            acc[j][3] = fma2(a1, bb[1][1].y, acc[j][3]);
            acc[j][0] = fma2(a2, bb[2][0].x, acc[j][0]);
            acc[j][1] = fma2(a2, bb[2][0].y, acc[j][1]);
            acc[j][2] = fma2(a2, bb[2][1].x, acc[j][2]);
            acc[j][3] = fma2(a2, bb[2][1].y, acc[j][3]);
            acc[j][0] = fma2(a3, bb[3][0].x, acc[j][0]);
            acc[j][1] = fma2(a3, bb[3][0].y, acc[j][1]);
            acc[j][2] = fma2(a3, bb[3][1].x, acc[j][2]);
            acc[j][3] = fma2(a3, bb[3][1].y, acc[j][3]);
        }
    }

    // epilogue: mask, tile max (16-lane reduce), store exp(s - mx), stats
    const float* mrow = mask + (size_t)b * TS * TS;
#pragma unroll
    for (int j = 0; j < 8; j++) {
        int q = qBase + ty + 16 * j;
        const float* mpl = mrow + (size_t)q * TS + kBase + tx * 4;        // k lo
        const float* mph = mpl + 64;                                      // k hi
        float4 m0 = *(const float4*)(mpl);
        float4 m1 = *(const float4*)(mph);
        float2 p0 = unpk(acc[j][0]), p1 = unpk(acc[j][1]);
        float2 p2 = unpk(acc[j][2]), p3 = unpk(acc[j][3]);
        float s0 = fmaf(p0.x, 0.125f, (m0.x - 1.0f) * 1e9f);
        float s1 = fmaf(p0.y, 0.125f, (m0.y - 1.0f) * 1e9f);
        float s2 = fmaf(p1.x, 0.125f, (m0.z - 1.0f) * 1e9f);
        float s3 = fmaf(p1.y, 0.125f, (m0.w - 1.0f) * 1e9f);
        float s4 = fmaf(p2.x, 0.125f, (m1.x - 1.0f) * 1e9f);
        float s5 = fmaf(p2.y, 0.125f, (m1.y - 1.0f) * 1e9f);
        float s6 = fmaf(p3.x, 0.125f, (m1.z - 1.0f) * 1e9f);
        float s7 = fmaf(p3.y, 0.125f, (m1.w - 1.0f) * 1e9f);

        float mx = fmaxf(fmaxf(fmaxf(s0, s1), fmaxf(s2, s3)),
                         fmaxf(fmaxf(s4, s5), fmaxf(s6, s7)));
#pragma unroll
        for (int o = 8; o > 0; o >>= 1)
            mx = fmaxf(mx, __shfl_xor_sync(0xffffffffu, mx, o));
        float t0 = __expf(s0 - mx), t1 = __expf(s1 - mx);
        float t2 = __expf(s2 - mx), t3 = __expf(s3 - mx);
        float t4 = __expf(s4 - mx), t5 = __expf(s5 - mx);
        float t6 = __expf(s6 - mx), t7 = __expf(s7 - mx);
        float* op = scores + ((size_t)bh * TS + q) * TS + kBase + tx * 4;
        *(float4*)(op)      = make_float4(t0, t1, t2, t3);
        *(float4*)(op + 64) = make_float4(t4, t5, t6, t7);
        float e = t0 + t1 + t2 + t3 + t4 + t5 + t6 + t7;
#pragma unroll
        for (int o = 8; o > 0; o >>= 1)
            e += __shfl_xor_sync(0xffffffffu, e, o);
        if (tx == 0)
            g_part[((size_t)bh * TS + q) * 16 + blockIdx.x] = make_float2(mx, e);
    }
}

// ---------------- K2: tile partials -> per-(row,ktile) rescale ---------------
__global__ __launch_bounds__(256) void reduce_kernel() {
    unsigned row = blockIdx.x * 256u + threadIdx.x;
    const float2* pp = &g_part[(size_t)row * 16];
    float2 p[16];
#pragma unroll
    for (int t = 0; t < 16; t++) p[t] = pp[t];
    float m = p[0].x;
#pragma unroll
    for (int t = 1; t < 16; t++) m = fmaxf(m, p[t].x);
    float s = 0.f;
#pragma unroll
    for (int t = 0; t < 16; t++) s += p[t].y * __expf(p[t].x - m);
    float inv = 1.0f / s;
#pragma unroll
    for (int t = 0; t < 16; t++)
        g_scale[(size_t)row * 16 + t] = __expf(p[t].x - m) * inv;
}

// ---------------- K3: pipelined rescale + INLINE threefry dropout + PV -------
// (unchanged: 64q x 64dv, 256 thr, 4 blocks/SM)
__global__ __launch_bounds__(256, 4) void context_kernel(
    const float* __restrict__ V, float* __restrict__ attn, float* __restrict__ ctx) {
    extern __shared__ float sm[];
    float* Ps  = sm;                       // [64][68]
    float* Vs  = sm + 64 * 68;             // [64][68]
    float* scs = sm + 128 * 68;            // [64][16]

    const int bh    = blockIdx.z;
    const int qBase = blockIdx.x * 64;
    const int tid   = threadIdx.x;
    const int tx    = tid & 15, ty = tid >> 4;

#pragma unroll
    for (int i = 0; i < 4; i++) {
        int x = tid + i * 256;
        scs[x] = g_scale[((size_t)bh * TS + qBase + (x >> 4)) * 16 + (x & 15)];
    }
    __syncthreads();

    unsigned long long acc2[4][2];
#pragma unroll
    for (int j = 0; j < 4; j++) { acc2[j][0] = 0ull; acc2[j][1] = 0ull; }

    const float* Vg = V + (size_t)bh * TS * TDK;

    float4 atv[4];
#pragma unroll
    for (int i = 0; i < 4; i++) {
        int f = tid + i * 256, r = f >> 4, c4 = f & 15;
        size_t off = ((size_t)bh * TS + qBase + r) * TS + c4 * 4;
        atv[i] = *(const float4*)(attn + off);
    }

    for (int c = 0; c < 32; c++) {
        const int kBase = c * 64;
#pragma unroll
        for (int i = 0; i < 4; i++) {
            int f = tid + i * 256, r = f >> 4, c4 = f & 15;
            float4 vq = *(const float4*)(Vg + (size_t)(kBase + r) * TDK + c4 * 4);
            *(float4*)(Vs + r * 68 + c4 * 4) = vq;

            int q = qBase + r, k = kBase + c4 * 4;
            size_t off = ((size_t)bh * TS + q) * TS + k;
            unsigned e0 = (unsigned)off;
            float sc = scs[r * 16 + (c >> 1)];
            float4 p;
            p.x = atv[i].x * sc; p.y = atv[i].y * sc;
            p.z = atv[i].z * sc; p.w = atv[i].w * sc;
            *(float4*)(attn + off) = p;               // normalized attn out
            float4 pd;
            pd.x = p.x * keep2x(e0);
            pd.y = p.y * keep2x(e0 + 1u);
            pd.z = p.z * keep2x(e0 + 2u);
            pd.w = p.w * keep2x(e0 + 3u);
            *(float4*)(Ps + r * 68 + c4 * 4) = pd;
        }
        __syncthreads();

        if (c < 31) {
            const int kn = (c + 1) * 64;
#pragma unroll
            for (int i = 0; i < 4; i++) {
                int f = tid + i * 256, r = f >> 4, c4 = f & 15;
                size_t off = ((size_t)bh * TS + qBase + r) * TS + kn + c4 * 4;
                atv[i] = *(const float4*)(attn + off);
            }
        }

#pragma unroll
        for (int kk4 = 0; kk4 < 16; kk4++) {
            float4 av[4];
#pragma unroll
            for (int j = 0; j < 4; j++)
                av[j] = *(const float4*)(Ps + (ty + 16 * j) * 68 + kk4 * 4);
#pragma unroll
            for (int t = 0; t < 4; t++) {
                ulonglong2 bv = *(const ulonglong2*)(Vs + (kk4 * 4 + t) * 68 + tx * 4);
#pragma unroll
                for (int j = 0; j < 4; j++) {
                    float as = (t == 0) ? av[j].x : (t == 1) ? av[j].y :
                               (t == 2) ? av[j].z : av[j].w;
                    unsigned long long a2 = dup2(as);
                    acc2[j][0] = fma2(a2, bv.x, acc2[j][0]);
                    acc2[j][1] = fma2(a2, bv.y, acc2[j][1]);
                }
            }
        }
        __syncthreads();
    }

#pragma unroll
    for (int j = 0; j < 4; j++) {
        int q = qBase + ty + 16 * j;
        float2 lo = unpk(acc2[j][0]), hi = unpk(acc2[j][1]);
        *(float4*)(ctx + ((size_t)bh * TS + q) * TDK + tx * 4) =
            make_float4(lo.x, lo.y, hi.x, hi.y);
    }
}

// ---------------- launch -----------------------------------------------------
extern "C" void kernel_launch(void* const* d_in, const int* in_sizes, int n_in,
                              void* d_out, int out_size) {
    const float* Q    = (const float*)d_in[0];
    const float* K    = (const float*)d_in[1];
    const float* V    = (const float*)d_in[2];
    const float* mask = (const float*)d_in[3];

    float* ctx  = (float*)d_out;            // context first (reference return order)
    float* attn = ctx + CTX_ELEMS;          // then attn; also used as scores scratch

    cudaFuncSetAttribute(scores_kernel,  cudaFuncAttributeMaxDynamicSharedMemorySize, 68608);
    cudaFuncSetAttribute(context_kernel, cudaFuncAttributeMaxDynamicSharedMemorySize, 38912);

    scores_kernel<<<dim3(16, 16, 32), 256, 68608>>>(Q, K, mask, attn);
    reduce_kernel<<<256, 256>>>();
    context_kernel<<<dim3(32, 1, 32), 256, 38912>>>(V, attn, ctx);
}